// round 15
// baseline (speedup 1.0000x reference)
#include <cuda_runtime.h>
#include <math.h>

#define NFEAT 500
#define DFULL 128
#define NCAP  8
#define DD    16
#define MNB   32
#define RIT   6
#define CUTN  5
#define NMAX  20000
#define NCLASS 16

typedef unsigned long long u64;

// ---- packed f32x2 helpers (sm_100+) ----
__device__ __forceinline__ u64 pack2(float lo, float hi) {
    u64 r; asm("mov.b64 %0, {%1, %2};" : "=l"(r) : "f"(lo), "f"(hi)); return r;
}
__device__ __forceinline__ void unpack2(u64 v, float& lo, float& hi) {
    asm("mov.b64 {%0, %1}, %2;" : "=f"(lo), "=f"(hi) : "l"(v));
}
__device__ __forceinline__ u64 fma2(u64 a, u64 b, u64 c) {
    u64 d; asm("fma.rn.f32x2 %0, %1, %2, %3;" : "=l"(d) : "l"(a), "l"(b), "l"(c)); return d;
}
__device__ __forceinline__ u64 add2(u64 a, u64 b) {
    u64 d; asm("add.rn.f32x2 %0, %1, %2;" : "=l"(d) : "l"(a), "l"(b)); return d;
}
__device__ __forceinline__ u64 mul2(u64 a, u64 b) {
    u64 d; asm("mul.rn.f32x2 %0, %1, %2;" : "=l"(d) : "l"(a), "l"(b)); return d;
}

// ---- scratch ----
__device__ float g_h  [NMAX * DFULL];
__device__ float g_xn0[NMAX * DFULL];
__device__ float g_xn1[NMAX * DFULL];
__device__ float g_u  [NMAX * DFULL];
__device__ float g_T  [NMAX * DD];
__device__ unsigned char g_arg[NMAX * CUTN];
__device__ float g_attn;
__device__ int   g_odd_nonzero = 0;  // monotone 0->1; set each run before consumers

// =====================================================================
// K1: h = x @ pca_w + pca_b. BM=64, BN=128, BK=16, 256 thr (known-good).
// nb dtype detection folded into the prologue.
// =====================================================================
__global__ void __launch_bounds__(256, 2)
k_gemm_pca(const float* __restrict__ x,
           const float* __restrict__ W,
           const float* __restrict__ bias,
           const int* __restrict__ nb32,
           int n_pairs,
           int n)
{
    __shared__ float As[2][16][72];
    __shared__ float Bs[2][16][128];

    int tid = threadIdx.x;
    int tx = tid & 15;
    int ty = tid >> 4;
    int row0 = blockIdx.x * 64;

    if (blockIdx.x == 0 && tid == 0) g_attn = 0.f;

    // folded nb dtype detection
    {
        int base = (blockIdx.x * blockDim.x + tid) * 4;
        int found = 0;
#pragma unroll
        for (int i = 0; i < 4; i++) {
            int p = base + i;
            if (p < n_pairs && nb32[2 * p + 1] != 0) found = 1;
        }
        if (found) atomicOr(&g_odd_nonzero, 1);
    }

    const int NT = (NFEAT + 15) / 16;

    float4 ra, rb[2];
    auto load_regs = [&](int kt) {
        {
            int r = tid >> 2;
            int q = (tid & 3) * 4;
            int grow = row0 + r;
            int col = kt + q;
            float4 v = make_float4(0.f, 0.f, 0.f, 0.f);
            if (grow < n && col + 3 < NFEAT)
                v = *(const float4*)(x + (size_t)grow * NFEAT + col);
            ra = v;
        }
#pragma unroll
        for (int i = 0; i < 2; i++) {
            int idx = tid * 2 + i;
            int rr = idx >> 5;
            int cq = (idx & 31) * 4;
            float4 w4 = make_float4(0.f, 0.f, 0.f, 0.f);
            if (kt + rr < NFEAT)
                w4 = *(const float4*)(W + (size_t)(kt + rr) * DFULL + cq);
            rb[i] = w4;
        }
    };
    auto store_smem = [&](int buf) {
        {
            int r = tid >> 2;
            int q = (tid & 3) * 4;
            As[buf][q + 0][r] = ra.x; As[buf][q + 1][r] = ra.y;
            As[buf][q + 2][r] = ra.z; As[buf][q + 3][r] = ra.w;
        }
#pragma unroll
        for (int i = 0; i < 2; i++) {
            int idx = tid * 2 + i;
            int rr = idx >> 5;
            int cq = (idx & 31) * 4;
            *(float4*)&Bs[buf][rr][cq] = rb[i];
        }
    };

    u64 acc2[4][4];
#pragma unroll
    for (int r = 0; r < 4; r++)
#pragma unroll
        for (int cp = 0; cp < 4; cp++) acc2[r][cp] = 0ull;

    load_regs(0);
    store_smem(0);
    __syncthreads();

    for (int t = 0; t < NT; t++) {
        int cur = t & 1;
        if (t + 1 < NT) load_regs((t + 1) * 16);

#pragma unroll
        for (int kk = 0; kk < 16; kk++) {
            float4 a4 = *(float4*)&As[cur][kk][ty * 4];
            u64 ad[4];
            ad[0] = pack2(a4.x, a4.x); ad[1] = pack2(a4.y, a4.y);
            ad[2] = pack2(a4.z, a4.z); ad[3] = pack2(a4.w, a4.w);
            ulonglong2 bp0 = *(ulonglong2*)&Bs[cur][kk][tx * 8];
            ulonglong2 bp1 = *(ulonglong2*)&Bs[cur][kk][tx * 8 + 4];
            u64 bd[4] = {bp0.x, bp0.y, bp1.x, bp1.y};
#pragma unroll
            for (int r = 0; r < 4; r++)
#pragma unroll
                for (int cp = 0; cp < 4; cp++)
                    acc2[r][cp] = fma2(ad[r], bd[cp], acc2[r][cp]);
        }

        if (t + 1 < NT) store_smem(cur ^ 1);
        __syncthreads();
    }

    float4 b0 = *(const float4*)(bias + tx * 8);
    float4 b1 = *(const float4*)(bias + tx * 8 + 4);
    u64 bb[4] = {pack2(b0.x, b0.y), pack2(b0.z, b0.w),
                 pack2(b1.x, b1.y), pack2(b1.z, b1.w)};
#pragma unroll
    for (int r = 0; r < 4; r++) {
        int grow = row0 + ty * 4 + r;
        if (grow < n) {
            ulonglong2 o0, o1;
            o0.x = add2(acc2[r][0], bb[0]); o0.y = add2(acc2[r][1], bb[1]);
            o1.x = add2(acc2[r][2], bb[2]); o1.y = add2(acc2[r][3], bb[3]);
            *(ulonglong2*)(g_h + (size_t)grow * DFULL + tx * 8)     = o0;
            *(ulonglong2*)(g_h + (size_t)grow * DFULL + tx * 8 + 4) = o1;
        }
    }
}

// =====================================================================
// K2: attention loss + xn0 = normalize(relu(h))
// =====================================================================
__global__ void k_attn_xn0(const float* __restrict__ ln_g,
                           const float* __restrict__ ln_b,
                           const float* __restrict__ wqs,
                           const float* __restrict__ wks,
                           int n)
{
    __shared__ float sQ[8][128];
    __shared__ float sH[8][128];
    __shared__ float sS[8][64];
    __shared__ float s_wq[256], s_wk[256];
    __shared__ float s_g[16], s_b[16];
    __shared__ float blk_acc;

    int tid = threadIdx.x;
    { s_wq[tid] = wqs[tid]; s_wk[tid] = wks[tid]; }
    if (tid < 16)  { s_g[tid] = ln_g[tid]; s_b[tid] = ln_b[tid]; }
    if (tid == 0)  blk_acc = 0.f;
    __syncthreads();

    int wp = tid >> 5, lane = tid & 31;
    int v = blockIdx.x * 8 + wp;
    if (v < n) {
        int a  = lane >> 2;
        int c0 = (lane & 3) * 4;
        float4 h4 = *(const float4*)(g_h + (size_t)v * DFULL + lane * 4);
        float hv[4] = {h4.x, h4.y, h4.z, h4.w};

        float s1 = hv[0] + hv[1] + hv[2] + hv[3];
        float s2 = hv[0]*hv[0] + hv[1]*hv[1] + hv[2]*hv[2] + hv[3]*hv[3];
        s1 += __shfl_xor_sync(0xffffffffu, s1, 1);
        s1 += __shfl_xor_sync(0xffffffffu, s1, 2);
        s2 += __shfl_xor_sync(0xffffffffu, s2, 1);
        s2 += __shfl_xor_sync(0xffffffffu, s2, 2);
        float mu  = s1 * (1.f / 16.f);
        float var = s2 * (1.f / 16.f) - mu * mu;
        float inv = rsqrtf(var + 1e-6f);
        float qn[4];
#pragma unroll
        for (int i = 0; i < 4; i++)
            qn[i] = (hv[i] - mu) * inv * s_g[c0 + i] + s_b[c0 + i];

#pragma unroll
        for (int i = 0; i < 4; i++) {
            sQ[wp][lane * 4 + i] = qn[i];
            sH[wp][lane * 4 + i] = hv[i];
        }
        __syncwarp();

        float q4[4] = {0.f, 0.f, 0.f, 0.f};
        float k4[4] = {0.f, 0.f, 0.f, 0.f};
#pragma unroll
        for (int j = 0; j < 16; j++) {
            float qa = sQ[wp][a * 16 + j];
            float ha = sH[wp][a * 16 + j];
#pragma unroll
            for (int i = 0; i < 4; i++) {
                q4[i] = fmaf(qa, s_wq[j * 16 + c0 + i], q4[i]);
                k4[i] = fmaf(ha, s_wk[j * 16 + c0 + i], k4[i]);
            }
        }
        __syncwarp();
#pragma unroll
        for (int i = 0; i < 4; i++) {
            sQ[wp][lane * 4 + i] = q4[i];
            sH[wp][lane * 4 + i] = k4[i];
        }
        __syncwarp();

        float sc[2];
#pragma unroll
        for (int r = 0; r < 2; r++) {
            int id = lane * 2 + r;
            int aa = id >> 3, bb = id & 7;
            float s = 0.f;
#pragma unroll
            for (int c = 0; c < 16; c++)
                s = fmaf(sQ[wp][aa * 16 + c], sH[wp][bb * 16 + c], s);
            sc[r] = s * 0.25f;
        }
        sS[wp][lane * 2 + 0] = sc[0];
        sS[wp][lane * 2 + 1] = sc[1];
        __syncwarp();

        float contrib = 0.f;
        if (lane < 8) {
            float mx = -1e30f;
#pragma unroll
            for (int b = 0; b < 8; b++) mx = fmaxf(mx, sS[wp][lane * 8 + b]);
            float sum = 0.f;
#pragma unroll
            for (int b = 0; b < 8; b++) sum += expf(sS[wp][lane * 8 + b] - mx);
            float diag = expf(sS[wp][lane * 8 + lane] - mx) / sum;
            contrib = 1.f - diag;
        }
        contrib += __shfl_xor_sync(0xffffffffu, contrib, 1);
        contrib += __shfl_xor_sync(0xffffffffu, contrib, 2);
        contrib += __shfl_xor_sync(0xffffffffu, contrib, 4);
        if (lane == 0) atomicAdd(&blk_acc, contrib);

        float r4[4];
#pragma unroll
        for (int i = 0; i < 4; i++) r4[i] = fmaxf(hv[i], 0.f);
        float ss = r4[0]*r4[0] + r4[1]*r4[1] + r4[2]*r4[2] + r4[3]*r4[3];
        ss += __shfl_xor_sync(0xffffffffu, ss, 1);
        ss += __shfl_xor_sync(0xffffffffu, ss, 2);
        float scale = 1.f / fmaxf(sqrtf(ss), 1e-12f);
        float4 o = make_float4(r4[0]*scale, r4[1]*scale, r4[2]*scale, r4[3]*scale);
        *(float4*)(g_xn0 + (size_t)v * DFULL + lane * 4) = o;
    }
    __syncthreads();
    if (tid == 0) atomicAdd(&g_attn, blk_acc);
}

// =====================================================================
// K3/K4: routing — ONE node per 64-thr block (2 warps). z for
// neighbors mm 0,1 in regs; mm 2,3 in per-thread-private transposed
// smem (z_s[(mm*8+c)*64+tid], 8B lane stride = conflict-free, no
// barrier needed). Regs drop ~122 -> ~90 -> ~10 blocks/SM (20 warps).
// Same math as R9/R12.
// =====================================================================
template <bool LAST>
__global__ void __launch_bounds__(64)
k_routing(const float* __restrict__ xn,
          const int* __restrict__ nb32,
          float* __restrict__ xn_out,
          int n)
{
    __shared__ u64   z_s[2 * 8 * 64];       // 8 KB: [mm-2][c][tid]
    __shared__ float part[2][2][8][16];     // 4 KB: [buf][w][k][c]

    int t = threadIdx.x;                    // 0..63
    int w = t >> 5;
    int lane = t & 31;
    int g = lane >> 3;
    int k = lane & 7;

    int v = blockIdx.x;                     // grid == n
    int st = g_odd_nonzero ? 1 : 2;

    float4 x3q4 = *(const float4*)(xn + (size_t)v * DFULL + k * DD + g * 4);
    float x3q[4] = {x3q4.x, x3q4.y, x3q4.z, x3q4.w};

    // gather z for 4 neighbors, quads permuted [g, g^1, g^2, g^3];
    // mm 0,1 -> regs, mm 2,3 -> smem
    u64 z2[2][8];
#pragma unroll
    for (int mm = 0; mm < 4; mm++) {
        int m = w * 16 + mm * 4 + g;
        int nbv = nb32[((size_t)v * MNB + m) * (size_t)st];
        u64 zrow[8];
        if (nbv >= 0) {
            const float* base = xn + (size_t)nbv * DFULL + k * DD;
#pragma unroll
            for (int q = 0; q < 4; q++) {
                int qg = g ^ q;
                float4 t4 = *(const float4*)(base + qg * 4);
                zrow[q * 2]     = pack2(t4.x, t4.y);
                zrow[q * 2 + 1] = pack2(t4.z, t4.w);
            }
        } else {
#pragma unroll
            for (int i = 0; i < 8; i++) zrow[i] = 0ull;
        }
        if (mm < 2) {
#pragma unroll
            for (int i = 0; i < 8; i++) z2[mm][i] = zrow[i];
        } else {
#pragma unroll
            for (int i = 0; i < 8; i++)
                z_s[((mm - 2) * 8 + i) * 64 + t] = zrow[i];
        }
    }

    u64 u2[8];
#pragma unroll
    for (int i = 0; i < 8; i++) u2[i] = 0ull;
    float nsq = 0.f;

    const u64 c0125 = pack2(0.125f, 0.125f);

    for (int it = 0; it < RIT; it++) {
        u64 acc2[8];
        if (it == 0) {
#pragma unroll
            for (int c = 0; c < 8; c++) {
                u64 za = z_s[(0 * 8 + c) * 64 + t];
                u64 zb = z_s[(1 * 8 + c) * 64 + t];
                acc2[c] = mul2(add2(add2(z2[0][c], z2[1][c]),
                                    add2(za, zb)), c0125);
            }
        } else {
            float invn = rsqrtf(fmaxf(nsq, 1e-24f));

            float s[4];
#pragma unroll
            for (int mm = 0; mm < 2; mm++) {
                u64 d0 = mul2(z2[mm][0], u2[0]);
                u64 d1 = mul2(z2[mm][1], u2[1]);
                d0 = fma2(z2[mm][2], u2[2], d0);
                d1 = fma2(z2[mm][3], u2[3], d1);
                d0 = fma2(z2[mm][4], u2[4], d0);
                d1 = fma2(z2[mm][5], u2[5], d1);
                d0 = fma2(z2[mm][6], u2[6], d0);
                d1 = fma2(z2[mm][7], u2[7], d1);
                d0 = add2(d0, d1);
                float lo, hi; unpack2(d0, lo, hi);
                s[mm] = (lo + hi) * invn;
            }
#pragma unroll
            for (int mm = 2; mm < 4; mm++) {
                const u64* zp = &z_s[(mm - 2) * 8 * 64 + t];
                u64 d0 = mul2(zp[0 * 64], u2[0]);
                u64 d1 = mul2(zp[1 * 64], u2[1]);
                d0 = fma2(zp[2 * 64], u2[2], d0);
                d1 = fma2(zp[3 * 64], u2[3], d1);
                d0 = fma2(zp[4 * 64], u2[4], d0);
                d1 = fma2(zp[5 * 64], u2[5], d1);
                d0 = fma2(zp[6 * 64], u2[6], d0);
                d1 = fma2(zp[7 * 64], u2[7], d1);
                d0 = add2(d0, d1);
                float lo, hi; unpack2(d0, lo, hi);
                s[mm] = (lo + hi) * invn;
            }

            if (LAST && it == RIT - 1 && w == 0) {
#pragma unroll
                for (int mm = 0; mm < 2; mm++) {
                    float bs = s[mm]; int bk = k;
#pragma unroll
                    for (int d2 = 1; d2 <= 4; d2 <<= 1) {
                        float os = __shfl_xor_sync(0xffffffffu, bs, d2);
                        int   ok = __shfl_xor_sync(0xffffffffu, bk, d2);
                        if (os > bs || (os == bs && ok < bk)) { bs = os; bk = ok; }
                    }
                    int m = mm * 4 + g;
                    if (k == 0 && m < CUTN)
                        g_arg[(size_t)v * CUTN + m] = (unsigned char)bk;
                }
            }

            float p[4];
#pragma unroll
            for (int mm = 0; mm < 4; mm++) {
                float e = __expf(s[mm]);
                float sum = e;
                sum += __shfl_xor_sync(0xffffffffu, sum, 1);
                sum += __shfl_xor_sync(0xffffffffu, sum, 2);
                sum += __shfl_xor_sync(0xffffffffu, sum, 4);
                p[mm] = __fdividef(e, sum);
            }
            u64 p20 = pack2(p[0], p[0]);
            u64 p21 = pack2(p[1], p[1]);
            u64 p22 = pack2(p[2], p[2]);
            u64 p23 = pack2(p[3], p[3]);
#pragma unroll
            for (int c = 0; c < 8; c++) {
                u64 za = z_s[(0 * 8 + c) * 64 + t];
                u64 zb = z_s[(1 * 8 + c) * 64 + t];
                acc2[c] = fma2(p20, z2[0][c],
                          fma2(p21, z2[1][c],
                          fma2(p22, za, mul2(p23, zb))));
            }
        }

        float acc[16];
#pragma unroll
        for (int c = 0; c < 8; c++) unpack2(acc2[c], acc[2*c], acc[2*c+1]);

        // reduce-scatter over g (permuted: keep-low/send-high)
        float red[8];
#pragma unroll
        for (int j = 0; j < 8; j++)
            red[j] = acc[j] + __shfl_xor_sync(0xffffffffu, acc[8 + j], 16);
        float quad[4];
#pragma unroll
        for (int j = 0; j < 4; j++)
            quad[j] = red[j] + __shfl_xor_sync(0xffffffffu, red[4 + j], 8);

        int buf = it & 1;
        *(float4*)&part[buf][w][k][g * 4] =
            make_float4(quad[0], quad[1], quad[2], quad[3]);
        __syncthreads();

        float4 o4 = *(float4*)&part[buf][1 - w][k][g * 4];
        float oq[4] = {quad[0] + o4.x + x3q[0], quad[1] + o4.y + x3q[1],
                       quad[2] + o4.z + x3q[2], quad[3] + o4.w + x3q[3]};

        if (it == RIT - 1) {
            if (w == 0) {
                if (LAST) {
                    *(float4*)(g_u + (size_t)v * DFULL + k * DD + g * 4) =
                        make_float4(oq[0], oq[1], oq[2], oq[3]);
                } else {
                    float r0 = fmaxf(oq[0], 0.f), r1 = fmaxf(oq[1], 0.f);
                    float r2 = fmaxf(oq[2], 0.f), r3 = fmaxf(oq[3], 0.f);
                    float ssr = r0*r0 + r1*r1 + r2*r2 + r3*r3;
                    ssr += __shfl_xor_sync(0xffffffffu, ssr, 8);
                    ssr += __shfl_xor_sync(0xffffffffu, ssr, 16);
                    float sc = rsqrtf(fmaxf(ssr, 1e-24f));
                    *(float4*)(xn_out + (size_t)v * DFULL + k * DD + g * 4) =
                        make_float4(r0*sc, r1*sc, r2*sc, r3*sc);
                }
            }
        } else {
            float np = oq[0]*oq[0] + oq[1]*oq[1] + oq[2]*oq[2] + oq[3]*oq[3];
            np += __shfl_xor_sync(0xffffffffu, np, 8);
            np += __shfl_xor_sync(0xffffffffu, np, 16);
            nsq = np;

            float h8[8], f16[16];
#pragma unroll
            for (int j = 0; j < 4; j++) {
                h8[j] = oq[j];
                h8[4 + j] = __shfl_xor_sync(0xffffffffu, oq[j], 8);
            }
#pragma unroll
            for (int j = 0; j < 8; j++) {
                f16[j] = h8[j];
                f16[8 + j] = __shfl_xor_sync(0xffffffffu, h8[j], 16);
            }
#pragma unroll
            for (int i = 0; i < 8; i++)
                u2[i] = pack2(f16[2*i], f16[2*i + 1]);
        }
        // part double-buffered: next write to this buffer is after the
        // next barrier, past all reads.
    }
}

// =====================================================================
// K5: T[w,:] = sum_{j<5} xn1[nb[w,j], arg[w,j], :]
// =====================================================================
__global__ void k_compute_T(const int* __restrict__ nb32, int n)
{
    int tid = blockIdx.x * blockDim.x + threadIdx.x;
    if (tid >= n * DD) return;
    int w = tid >> 4, c = tid & 15;
    int st = g_odd_nonzero ? 1 : 2;
    float s = 0.f;
#pragma unroll
    for (int j = 0; j < CUTN; j++) {
        int nv = nb32[((size_t)w * MNB + j) * (size_t)st];
        if (nv >= 0) {
            int a = g_arg[(size_t)w * CUTN + j];
            s += g_xn1[(size_t)nv * DFULL + a * DD + c];
        }
    }
    g_T[tid] = s;
}

// =====================================================================
// K6: meta + logits + log_softmax + attn scalar
// =====================================================================
__global__ void k_meta_out(const int* __restrict__ nb32,
                           const float* __restrict__ mlp_w,
                           const float* __restrict__ mlp_b,
                           float* __restrict__ out,
                           int n)
{
    __shared__ float s_w[128 * 16];
    __shared__ float s_b[16];
    __shared__ float sM[8][128];

    int tid = threadIdx.x;
    for (int i = tid; i < 2048; i += 256) s_w[i] = mlp_w[i];
    if (tid < 16) s_b[tid] = mlp_b[tid];
    __syncthreads();

    int st = g_odd_nonzero ? 1 : 2;
    int wp = tid >> 5, lane = tid & 31;
    int v = blockIdx.x * 8 + wp;
    if (v < n) {
        int a = lane >> 2;
        float4 acc = *(const float4*)(g_u + (size_t)v * DFULL + lane * 4);
        const float inv25 = 1.f / 25.f;
#pragma unroll
        for (int j = 0; j < CUTN; j++) {
            int nv = nb32[((size_t)v * MNB + j) * (size_t)st];
            if (nv >= 0) {
                int aj = g_arg[(size_t)v * CUTN + j];
                if (aj == a) {
                    float4 t4 = *(const float4*)(g_T + (size_t)nv * DD + (lane & 3) * 4);
                    acc.x = fmaf(inv25, t4.x, acc.x);
                    acc.y = fmaf(inv25, t4.y, acc.y);
                    acc.z = fmaf(inv25, t4.z, acc.z);
                    acc.w = fmaf(inv25, t4.w, acc.w);
                }
            }
        }
        acc.x = fmaxf(acc.x, 0.f); acc.y = fmaxf(acc.y, 0.f);
        acc.z = fmaxf(acc.z, 0.f); acc.w = fmaxf(acc.w, 0.f);
        *(float4*)&sM[wp][lane * 4] = acc;
        __syncwarp();

        float logit = 0.f;
        if (lane < 16) {
            logit = s_b[lane];
            for (int f = 0; f < 128; f++)
                logit = fmaf(sM[wp][f], s_w[f * 16 + lane], logit);
            out[(size_t)n * 16 + 1 + (size_t)v * 16 + lane] = logit;
        }
        float mx = (lane < 16) ? logit : -1e30f;
        mx = fmaxf(mx, __shfl_xor_sync(0xffffffffu, mx, 1));
        mx = fmaxf(mx, __shfl_xor_sync(0xffffffffu, mx, 2));
        mx = fmaxf(mx, __shfl_xor_sync(0xffffffffu, mx, 4));
        mx = fmaxf(mx, __shfl_xor_sync(0xffffffffu, mx, 8));
        float e = (lane < 16) ? expf(logit - mx) : 0.f;
        float sum = e;
        sum += __shfl_xor_sync(0xffffffffu, sum, 1);
        sum += __shfl_xor_sync(0xffffffffu, sum, 2);
        sum += __shfl_xor_sync(0xffffffffu, sum, 4);
        sum += __shfl_xor_sync(0xffffffffu, sum, 8);
        if (lane < 16)
            out[(size_t)v * 16 + lane] = (logit - mx) - logf(sum);
    }
    if (blockIdx.x == 0 && tid == 0)
        out[(size_t)n * 16] = g_attn / (56.f * (float)n);
}

// =====================================================================
extern "C" void kernel_launch(void* const* d_in, const int* in_sizes, int n_in,
                              void* d_out, int out_size)
{
    const float* x     = (const float*)d_in[0];
    const int*   nb32  = (const int*)d_in[1];
    const float* pca_w = (const float*)d_in[2];
    const float* pca_b = (const float*)d_in[3];
    const float* ln_g  = (const float*)d_in[4];
    const float* ln_b  = (const float*)d_in[5];
    const float* w_qs  = (const float*)d_in[6];
    const float* w_ks  = (const float*)d_in[7];
    const float* mlp_w = (const float*)d_in[8];
    const float* mlp_b = (const float*)d_in[9];
    float* out = (float*)d_out;

    int n = in_sizes[0] / NFEAT;   // 20000
    int n_nb = in_sizes[1];

    float* p_xn0; cudaGetSymbolAddress((void**)&p_xn0, g_xn0);
    float* p_xn1; cudaGetSymbolAddress((void**)&p_xn1, g_xn1);

    k_gemm_pca<<<(n + 63) / 64, 256>>>(x, pca_w, pca_b, nb32, n_nb / 2, n);
    k_attn_xn0<<<(n + 7) / 8, 256>>>(ln_g, ln_b, w_qs, w_ks, n);
    k_routing<false><<<n, 64>>>(p_xn0, nb32, p_xn1, n);
    k_routing<true ><<<n, 64>>>(p_xn1, nb32, nullptr, n);
    k_compute_T<<<(n * DD + 255) / 256, 256>>>(nb32, n);
    k_meta_out<<<(n + 7) / 8, 256>>>(nb32, mlp_w, mlp_b, out, n);
}

// round 16
// speedup vs baseline: 1.0931x; 1.0931x over previous
#include <cuda_runtime.h>
#include <math.h>

#define NFEAT 500
#define DFULL 128
#define NCAP  8
#define DD    16
#define MNB   32
#define RIT   6
#define CUTN  5
#define NMAX  20000
#define NCLASS 16

typedef unsigned long long u64;

// ---- packed f32x2 helpers (sm_100+) ----
__device__ __forceinline__ u64 pack2(float lo, float hi) {
    u64 r; asm("mov.b64 %0, {%1, %2};" : "=l"(r) : "f"(lo), "f"(hi)); return r;
}
__device__ __forceinline__ void unpack2(u64 v, float& lo, float& hi) {
    asm("mov.b64 {%0, %1}, %2;" : "=f"(lo), "=f"(hi) : "l"(v));
}
__device__ __forceinline__ u64 fma2(u64 a, u64 b, u64 c) {
    u64 d; asm("fma.rn.f32x2 %0, %1, %2, %3;" : "=l"(d) : "l"(a), "l"(b), "l"(c)); return d;
}
__device__ __forceinline__ u64 add2(u64 a, u64 b) {
    u64 d; asm("add.rn.f32x2 %0, %1, %2;" : "=l"(d) : "l"(a), "l"(b)); return d;
}
__device__ __forceinline__ u64 mul2(u64 a, u64 b) {
    u64 d; asm("mul.rn.f32x2 %0, %1, %2;" : "=l"(d) : "l"(a), "l"(b)); return d;
}

// ---- scratch ----
__device__ float g_h  [NMAX * DFULL];
__device__ float g_xn0[NMAX * DFULL];
__device__ float g_xn1[NMAX * DFULL];
__device__ float g_u  [NMAX * DFULL];
__device__ float g_T  [NMAX * DD];
__device__ unsigned char g_arg[NMAX * CUTN];
__device__ float g_attn;
__device__ int   g_odd_nonzero = 0;  // monotone 0->1; set each run before consumers

// =====================================================================
// K1: h = x @ pca_w + pca_b. BM=64, BN=128, BK=16, 256 thr (known-good).
// nb dtype detection folded into the prologue.
// =====================================================================
__global__ void __launch_bounds__(256, 2)
k_gemm_pca(const float* __restrict__ x,
           const float* __restrict__ W,
           const float* __restrict__ bias,
           const int* __restrict__ nb32,
           int n_pairs,
           int n)
{
    __shared__ float As[2][16][72];
    __shared__ float Bs[2][16][128];

    int tid = threadIdx.x;
    int tx = tid & 15;
    int ty = tid >> 4;
    int row0 = blockIdx.x * 64;

    if (blockIdx.x == 0 && tid == 0) g_attn = 0.f;

    // folded nb dtype detection
    {
        int base = (blockIdx.x * blockDim.x + tid) * 4;
        int found = 0;
#pragma unroll
        for (int i = 0; i < 4; i++) {
            int p = base + i;
            if (p < n_pairs && nb32[2 * p + 1] != 0) found = 1;
        }
        if (found) atomicOr(&g_odd_nonzero, 1);
    }

    const int NT = (NFEAT + 15) / 16;

    float4 ra, rb[2];
    auto load_regs = [&](int kt) {
        {
            int r = tid >> 2;
            int q = (tid & 3) * 4;
            int grow = row0 + r;
            int col = kt + q;
            float4 v = make_float4(0.f, 0.f, 0.f, 0.f);
            if (grow < n && col + 3 < NFEAT)
                v = *(const float4*)(x + (size_t)grow * NFEAT + col);
            ra = v;
        }
#pragma unroll
        for (int i = 0; i < 2; i++) {
            int idx = tid * 2 + i;
            int rr = idx >> 5;
            int cq = (idx & 31) * 4;
            float4 w4 = make_float4(0.f, 0.f, 0.f, 0.f);
            if (kt + rr < NFEAT)
                w4 = *(const float4*)(W + (size_t)(kt + rr) * DFULL + cq);
            rb[i] = w4;
        }
    };
    auto store_smem = [&](int buf) {
        {
            int r = tid >> 2;
            int q = (tid & 3) * 4;
            As[buf][q + 0][r] = ra.x; As[buf][q + 1][r] = ra.y;
            As[buf][q + 2][r] = ra.z; As[buf][q + 3][r] = ra.w;
        }
#pragma unroll
        for (int i = 0; i < 2; i++) {
            int idx = tid * 2 + i;
            int rr = idx >> 5;
            int cq = (idx & 31) * 4;
            *(float4*)&Bs[buf][rr][cq] = rb[i];
        }
    };

    u64 acc2[4][4];
#pragma unroll
    for (int r = 0; r < 4; r++)
#pragma unroll
        for (int cp = 0; cp < 4; cp++) acc2[r][cp] = 0ull;

    load_regs(0);
    store_smem(0);
    __syncthreads();

    for (int t = 0; t < NT; t++) {
        int cur = t & 1;
        if (t + 1 < NT) load_regs((t + 1) * 16);

#pragma unroll
        for (int kk = 0; kk < 16; kk++) {
            float4 a4 = *(float4*)&As[cur][kk][ty * 4];
            u64 ad[4];
            ad[0] = pack2(a4.x, a4.x); ad[1] = pack2(a4.y, a4.y);
            ad[2] = pack2(a4.z, a4.z); ad[3] = pack2(a4.w, a4.w);
            ulonglong2 bp0 = *(ulonglong2*)&Bs[cur][kk][tx * 8];
            ulonglong2 bp1 = *(ulonglong2*)&Bs[cur][kk][tx * 8 + 4];
            u64 bd[4] = {bp0.x, bp0.y, bp1.x, bp1.y};
#pragma unroll
            for (int r = 0; r < 4; r++)
#pragma unroll
                for (int cp = 0; cp < 4; cp++)
                    acc2[r][cp] = fma2(ad[r], bd[cp], acc2[r][cp]);
        }

        if (t + 1 < NT) store_smem(cur ^ 1);
        __syncthreads();
    }

    float4 b0 = *(const float4*)(bias + tx * 8);
    float4 b1 = *(const float4*)(bias + tx * 8 + 4);
    u64 bb[4] = {pack2(b0.x, b0.y), pack2(b0.z, b0.w),
                 pack2(b1.x, b1.y), pack2(b1.z, b1.w)};
#pragma unroll
    for (int r = 0; r < 4; r++) {
        int grow = row0 + ty * 4 + r;
        if (grow < n) {
            ulonglong2 o0, o1;
            o0.x = add2(acc2[r][0], bb[0]); o0.y = add2(acc2[r][1], bb[1]);
            o1.x = add2(acc2[r][2], bb[2]); o1.y = add2(acc2[r][3], bb[3]);
            *(ulonglong2*)(g_h + (size_t)grow * DFULL + tx * 8)     = o0;
            *(ulonglong2*)(g_h + (size_t)grow * DFULL + tx * 8 + 4) = o1;
        }
    }
}

// =====================================================================
// K2: attention loss + xn0 = normalize(relu(h))
// =====================================================================
__global__ void k_attn_xn0(const float* __restrict__ ln_g,
                           const float* __restrict__ ln_b,
                           const float* __restrict__ wqs,
                           const float* __restrict__ wks,
                           int n)
{
    __shared__ float sQ[8][128];
    __shared__ float sH[8][128];
    __shared__ float sS[8][64];
    __shared__ float s_wq[256], s_wk[256];
    __shared__ float s_g[16], s_b[16];
    __shared__ float blk_acc;

    int tid = threadIdx.x;
    { s_wq[tid] = wqs[tid]; s_wk[tid] = wks[tid]; }
    if (tid < 16)  { s_g[tid] = ln_g[tid]; s_b[tid] = ln_b[tid]; }
    if (tid == 0)  blk_acc = 0.f;
    __syncthreads();

    int wp = tid >> 5, lane = tid & 31;
    int v = blockIdx.x * 8 + wp;
    if (v < n) {
        int a  = lane >> 2;
        int c0 = (lane & 3) * 4;
        float4 h4 = *(const float4*)(g_h + (size_t)v * DFULL + lane * 4);
        float hv[4] = {h4.x, h4.y, h4.z, h4.w};

        float s1 = hv[0] + hv[1] + hv[2] + hv[3];
        float s2 = hv[0]*hv[0] + hv[1]*hv[1] + hv[2]*hv[2] + hv[3]*hv[3];
        s1 += __shfl_xor_sync(0xffffffffu, s1, 1);
        s1 += __shfl_xor_sync(0xffffffffu, s1, 2);
        s2 += __shfl_xor_sync(0xffffffffu, s2, 1);
        s2 += __shfl_xor_sync(0xffffffffu, s2, 2);
        float mu  = s1 * (1.f / 16.f);
        float var = s2 * (1.f / 16.f) - mu * mu;
        float inv = rsqrtf(var + 1e-6f);
        float qn[4];
#pragma unroll
        for (int i = 0; i < 4; i++)
            qn[i] = (hv[i] - mu) * inv * s_g[c0 + i] + s_b[c0 + i];

#pragma unroll
        for (int i = 0; i < 4; i++) {
            sQ[wp][lane * 4 + i] = qn[i];
            sH[wp][lane * 4 + i] = hv[i];
        }
        __syncwarp();

        float q4[4] = {0.f, 0.f, 0.f, 0.f};
        float k4[4] = {0.f, 0.f, 0.f, 0.f};
#pragma unroll
        for (int j = 0; j < 16; j++) {
            float qa = sQ[wp][a * 16 + j];
            float ha = sH[wp][a * 16 + j];
#pragma unroll
            for (int i = 0; i < 4; i++) {
                q4[i] = fmaf(qa, s_wq[j * 16 + c0 + i], q4[i]);
                k4[i] = fmaf(ha, s_wk[j * 16 + c0 + i], k4[i]);
            }
        }
        __syncwarp();
#pragma unroll
        for (int i = 0; i < 4; i++) {
            sQ[wp][lane * 4 + i] = q4[i];
            sH[wp][lane * 4 + i] = k4[i];
        }
        __syncwarp();

        float sc[2];
#pragma unroll
        for (int r = 0; r < 2; r++) {
            int id = lane * 2 + r;
            int aa = id >> 3, bb = id & 7;
            float s = 0.f;
#pragma unroll
            for (int c = 0; c < 16; c++)
                s = fmaf(sQ[wp][aa * 16 + c], sH[wp][bb * 16 + c], s);
            sc[r] = s * 0.25f;
        }
        sS[wp][lane * 2 + 0] = sc[0];
        sS[wp][lane * 2 + 1] = sc[1];
        __syncwarp();

        float contrib = 0.f;
        if (lane < 8) {
            float mx = -1e30f;
#pragma unroll
            for (int b = 0; b < 8; b++) mx = fmaxf(mx, sS[wp][lane * 8 + b]);
            float sum = 0.f;
#pragma unroll
            for (int b = 0; b < 8; b++) sum += expf(sS[wp][lane * 8 + b] - mx);
            float diag = expf(sS[wp][lane * 8 + lane] - mx) / sum;
            contrib = 1.f - diag;
        }
        contrib += __shfl_xor_sync(0xffffffffu, contrib, 1);
        contrib += __shfl_xor_sync(0xffffffffu, contrib, 2);
        contrib += __shfl_xor_sync(0xffffffffu, contrib, 4);
        if (lane == 0) atomicAdd(&blk_acc, contrib);

        float r4[4];
#pragma unroll
        for (int i = 0; i < 4; i++) r4[i] = fmaxf(hv[i], 0.f);
        float ss = r4[0]*r4[0] + r4[1]*r4[1] + r4[2]*r4[2] + r4[3]*r4[3];
        ss += __shfl_xor_sync(0xffffffffu, ss, 1);
        ss += __shfl_xor_sync(0xffffffffu, ss, 2);
        float scale = 1.f / fmaxf(sqrtf(ss), 1e-12f);
        float4 o = make_float4(r4[0]*scale, r4[1]*scale, r4[2]*scale, r4[3]*scale);
        *(float4*)(g_xn0 + (size_t)v * DFULL + lane * 4) = o;
    }
    __syncthreads();
    if (tid == 0) atomicAdd(&g_attn, blk_acc);
}

// =====================================================================
// K3/K4: routing — EXACT R12 dataflow (known-good, ~121us/layer).
// =====================================================================
template <bool LAST>
__global__ void __launch_bounds__(128)
k_routing(const float* __restrict__ xn,
          const int* __restrict__ nb32,
          float* __restrict__ xn_out,
          int n)
{
    __shared__ float part[2][2][2][8][16];   // [buf][node][w][k][c]

    int t = threadIdx.x;
    int node = t >> 6;
    int w = (t >> 5) & 1;
    int lane = t & 31;
    int g = lane >> 3;
    int k = lane & 7;

    int v = blockIdx.x * 2 + node;
    bool valid = v < n;
    int vv = valid ? v : (n - 1);
    int st = g_odd_nonzero ? 1 : 2;

    float4 x3q4 = *(const float4*)(xn + (size_t)vv * DFULL + k * DD + g * 4);
    float x3q[4] = {x3q4.x, x3q4.y, x3q4.z, x3q4.w};

    u64 z2[4][8];
#pragma unroll
    for (int mm = 0; mm < 4; mm++) {
        int m = w * 16 + mm * 4 + g;
        int nbv = nb32[((size_t)vv * MNB + m) * (size_t)st];
        if (nbv >= 0) {
            const float* base = xn + (size_t)nbv * DFULL + k * DD;
#pragma unroll
            for (int q = 0; q < 4; q++) {
                int qg = g ^ q;
                float4 t4 = *(const float4*)(base + qg * 4);
                z2[mm][q * 2]     = pack2(t4.x, t4.y);
                z2[mm][q * 2 + 1] = pack2(t4.z, t4.w);
            }
        } else {
#pragma unroll
            for (int i = 0; i < 8; i++) z2[mm][i] = 0ull;
        }
    }

    u64 u2[8];
#pragma unroll
    for (int i = 0; i < 8; i++) u2[i] = 0ull;
    float nsq = 0.f;

    const u64 c0125 = pack2(0.125f, 0.125f);

    for (int it = 0; it < RIT; it++) {
        u64 acc2[8];
        if (it == 0) {
#pragma unroll
            for (int c = 0; c < 8; c++)
                acc2[c] = mul2(add2(add2(z2[0][c], z2[1][c]),
                                    add2(z2[2][c], z2[3][c])), c0125);
        } else {
            float invn = rsqrtf(fmaxf(nsq, 1e-24f));

            float s[4];
#pragma unroll
            for (int mm = 0; mm < 4; mm++) {
                u64 d0 = mul2(z2[mm][0], u2[0]);
                u64 d1 = mul2(z2[mm][1], u2[1]);
                d0 = fma2(z2[mm][2], u2[2], d0);
                d1 = fma2(z2[mm][3], u2[3], d1);
                d0 = fma2(z2[mm][4], u2[4], d0);
                d1 = fma2(z2[mm][5], u2[5], d1);
                d0 = fma2(z2[mm][6], u2[6], d0);
                d1 = fma2(z2[mm][7], u2[7], d1);
                d0 = add2(d0, d1);
                float lo, hi; unpack2(d0, lo, hi);
                s[mm] = (lo + hi) * invn;
            }

            if (LAST && it == RIT - 1 && w == 0) {
#pragma unroll
                for (int mm = 0; mm < 2; mm++) {
                    float bs = s[mm]; int bk = k;
#pragma unroll
                    for (int d2 = 1; d2 <= 4; d2 <<= 1) {
                        float os = __shfl_xor_sync(0xffffffffu, bs, d2);
                        int   ok = __shfl_xor_sync(0xffffffffu, bk, d2);
                        if (os > bs || (os == bs && ok < bk)) { bs = os; bk = ok; }
                    }
                    int m = mm * 4 + g;
                    if (k == 0 && m < CUTN && valid)
                        g_arg[(size_t)v * CUTN + m] = (unsigned char)bk;
                }
            }

            float p[4];
#pragma unroll
            for (int mm = 0; mm < 4; mm++) {
                float e = __expf(s[mm]);
                float sum = e;
                sum += __shfl_xor_sync(0xffffffffu, sum, 1);
                sum += __shfl_xor_sync(0xffffffffu, sum, 2);
                sum += __shfl_xor_sync(0xffffffffu, sum, 4);
                p[mm] = __fdividef(e, sum);
            }
            u64 p2[4];
#pragma unroll
            for (int mm = 0; mm < 4; mm++) p2[mm] = pack2(p[mm], p[mm]);
#pragma unroll
            for (int c = 0; c < 8; c++)
                acc2[c] = fma2(p2[0], z2[0][c],
                          fma2(p2[1], z2[1][c],
                          fma2(p2[2], z2[2][c], mul2(p2[3], z2[3][c]))));
        }

        float acc[16];
#pragma unroll
        for (int c = 0; c < 8; c++) unpack2(acc2[c], acc[2*c], acc[2*c+1]);

        float red[8];
#pragma unroll
        for (int j = 0; j < 8; j++)
            red[j] = acc[j] + __shfl_xor_sync(0xffffffffu, acc[8 + j], 16);
        float quad[4];
#pragma unroll
        for (int j = 0; j < 4; j++)
            quad[j] = red[j] + __shfl_xor_sync(0xffffffffu, red[4 + j], 8);

        int buf = it & 1;
        *(float4*)&part[buf][node][w][k][g * 4] =
            make_float4(quad[0], quad[1], quad[2], quad[3]);
        __syncthreads();

        float4 o4 = *(float4*)&part[buf][node][1 - w][k][g * 4];
        float oq[4] = {quad[0] + o4.x + x3q[0], quad[1] + o4.y + x3q[1],
                       quad[2] + o4.z + x3q[2], quad[3] + o4.w + x3q[3]};

        if (it == RIT - 1) {
            if (valid && w == 0) {
                if (LAST) {
                    *(float4*)(g_u + (size_t)v * DFULL + k * DD + g * 4) =
                        make_float4(oq[0], oq[1], oq[2], oq[3]);
                } else {
                    float r0 = fmaxf(oq[0], 0.f), r1 = fmaxf(oq[1], 0.f);
                    float r2 = fmaxf(oq[2], 0.f), r3 = fmaxf(oq[3], 0.f);
                    float ssr = r0*r0 + r1*r1 + r2*r2 + r3*r3;
                    ssr += __shfl_xor_sync(0xffffffffu, ssr, 8);
                    ssr += __shfl_xor_sync(0xffffffffu, ssr, 16);
                    float sc = rsqrtf(fmaxf(ssr, 1e-24f));
                    *(float4*)(xn_out + (size_t)v * DFULL + k * DD + g * 4) =
                        make_float4(r0*sc, r1*sc, r2*sc, r3*sc);
                }
            }
        } else {
            float np = oq[0]*oq[0] + oq[1]*oq[1] + oq[2]*oq[2] + oq[3]*oq[3];
            np += __shfl_xor_sync(0xffffffffu, np, 8);
            np += __shfl_xor_sync(0xffffffffu, np, 16);
            nsq = np;

            float h8[8], f16[16];
#pragma unroll
            for (int j = 0; j < 4; j++) {
                h8[j] = oq[j];
                h8[4 + j] = __shfl_xor_sync(0xffffffffu, oq[j], 8);
            }
#pragma unroll
            for (int j = 0; j < 8; j++) {
                f16[j] = h8[j];
                f16[8 + j] = __shfl_xor_sync(0xffffffffu, h8[j], 16);
            }
#pragma unroll
            for (int i = 0; i < 8; i++)
                u2[i] = pack2(f16[2*i], f16[2*i + 1]);
        }
    }
}

// =====================================================================
// K5: T[w,:] = sum_{j<5} xn1[nb[w,j], arg[w,j], :]
// =====================================================================
__global__ void k_compute_T(const int* __restrict__ nb32, int n)
{
    int tid = blockIdx.x * blockDim.x + threadIdx.x;
    if (tid >= n * DD) return;
    int w = tid >> 4, c = tid & 15;
    int st = g_odd_nonzero ? 1 : 2;
    float s = 0.f;
#pragma unroll
    for (int j = 0; j < CUTN; j++) {
        int nv = nb32[((size_t)w * MNB + j) * (size_t)st];
        if (nv >= 0) {
            int a = g_arg[(size_t)w * CUTN + j];
            s += g_xn1[(size_t)nv * DFULL + a * DD + c];
        }
    }
    g_T[tid] = s;
}

// =====================================================================
// K6: meta + logits + log_softmax + attn scalar.
// Logit dot split across all 32 lanes: lane = (half hh, class c);
// 64-FMA half-dot + one shfl_xor(16) -> full 128-dot on lanes 0..15.
// =====================================================================
__global__ void k_meta_out(const int* __restrict__ nb32,
                           const float* __restrict__ mlp_w,
                           const float* __restrict__ mlp_b,
                           float* __restrict__ out,
                           int n)
{
    __shared__ float s_w[128 * 16];
    __shared__ float s_b[16];
    __shared__ float sM[8][128];

    int tid = threadIdx.x;
    for (int i = tid; i < 2048; i += 256) s_w[i] = mlp_w[i];
    if (tid < 16) s_b[tid] = mlp_b[tid];
    __syncthreads();

    int st = g_odd_nonzero ? 1 : 2;
    int wp = tid >> 5, lane = tid & 31;
    int v = blockIdx.x * 8 + wp;
    if (v < n) {
        int a = lane >> 2;
        float4 acc = *(const float4*)(g_u + (size_t)v * DFULL + lane * 4);
        const float inv25 = 1.f / 25.f;
#pragma unroll
        for (int j = 0; j < CUTN; j++) {
            int nv = nb32[((size_t)v * MNB + j) * (size_t)st];
            if (nv >= 0) {
                int aj = g_arg[(size_t)v * CUTN + j];
                if (aj == a) {
                    float4 t4 = *(const float4*)(g_T + (size_t)nv * DD + (lane & 3) * 4);
                    acc.x = fmaf(inv25, t4.x, acc.x);
                    acc.y = fmaf(inv25, t4.y, acc.y);
                    acc.z = fmaf(inv25, t4.z, acc.z);
                    acc.w = fmaf(inv25, t4.w, acc.w);
                }
            }
        }
        acc.x = fmaxf(acc.x, 0.f); acc.y = fmaxf(acc.y, 0.f);
        acc.z = fmaxf(acc.z, 0.f); acc.w = fmaxf(acc.w, 0.f);
        *(float4*)&sM[wp][lane * 4] = acc;
        __syncwarp();

        // split dot: half hh = lane>>4 (f in [hh*64, hh*64+64)), class c = lane&15
        int hh = lane >> 4;
        int cc = lane & 15;
        float part = 0.f;
        int f0 = hh * 64;
#pragma unroll 16
        for (int f = 0; f < 64; f++)
            part = fmaf(sM[wp][f0 + f], s_w[(f0 + f) * 16 + cc], part);
        float logit = part + __shfl_xor_sync(0xffffffffu, part, 16) + s_b[cc];

        if (lane < 16)
            out[(size_t)n * 16 + 1 + (size_t)v * 16 + lane] = logit;

        float mx = (lane < 16) ? logit : -1e30f;
        mx = fmaxf(mx, __shfl_xor_sync(0xffffffffu, mx, 1));
        mx = fmaxf(mx, __shfl_xor_sync(0xffffffffu, mx, 2));
        mx = fmaxf(mx, __shfl_xor_sync(0xffffffffu, mx, 4));
        mx = fmaxf(mx, __shfl_xor_sync(0xffffffffu, mx, 8));
        float e = (lane < 16) ? expf(logit - mx) : 0.f;
        float sum = e;
        sum += __shfl_xor_sync(0xffffffffu, sum, 1);
        sum += __shfl_xor_sync(0xffffffffu, sum, 2);
        sum += __shfl_xor_sync(0xffffffffu, sum, 4);
        sum += __shfl_xor_sync(0xffffffffu, sum, 8);
        if (lane < 16)
            out[(size_t)v * 16 + lane] = (logit - mx) - logf(sum);
    }
    if (blockIdx.x == 0 && tid == 0)
        out[(size_t)n * 16] = g_attn / (56.f * (float)n);
}

// =====================================================================
extern "C" void kernel_launch(void* const* d_in, const int* in_sizes, int n_in,
                              void* d_out, int out_size)
{
    const float* x     = (const float*)d_in[0];
    const int*   nb32  = (const int*)d_in[1];
    const float* pca_w = (const float*)d_in[2];
    const float* pca_b = (const float*)d_in[3];
    const float* ln_g  = (const float*)d_in[4];
    const float* ln_b  = (const float*)d_in[5];
    const float* w_qs  = (const float*)d_in[6];
    const float* w_ks  = (const float*)d_in[7];
    const float* mlp_w = (const float*)d_in[8];
    const float* mlp_b = (const float*)d_in[9];
    float* out = (float*)d_out;

    int n = in_sizes[0] / NFEAT;   // 20000
    int n_nb = in_sizes[1];

    float* p_xn0; cudaGetSymbolAddress((void**)&p_xn0, g_xn0);
    float* p_xn1; cudaGetSymbolAddress((void**)&p_xn1, g_xn1);

    k_gemm_pca<<<(n + 63) / 64, 256>>>(x, pca_w, pca_b, nb32, n_nb / 2, n);
    k_attn_xn0<<<(n + 7) / 8, 256>>>(ln_g, ln_b, w_qs, w_ks, n);
    k_routing<false><<<(n + 1) / 2, 128>>>(p_xn0, nb32, p_xn1, n);
    k_routing<true ><<<(n + 1) / 2, 128>>>(p_xn1, nb32, nullptr, n);
    k_compute_T<<<(n * DD + 255) / 256, 256>>>(nb32, n);
    k_meta_out<<<(n + 7) / 8, 256>>>(nb32, mlp_w, mlp_b, out, n);
}

// round 17
// speedup vs baseline: 1.1123x; 1.0176x over previous
#include <cuda_runtime.h>
#include <math.h>

#define NFEAT 500
#define DFULL 128
#define NCAP  8
#define DD    16
#define MNB   32
#define RIT   6
#define CUTN  5
#define NMAX  20000
#define NCLASS 16

typedef unsigned long long u64;

// ---- packed f32x2 helpers (sm_100+) ----
__device__ __forceinline__ u64 pack2(float lo, float hi) {
    u64 r; asm("mov.b64 %0, {%1, %2};" : "=l"(r) : "f"(lo), "f"(hi)); return r;
}
__device__ __forceinline__ void unpack2(u64 v, float& lo, float& hi) {
    asm("mov.b64 {%0, %1}, %2;" : "=f"(lo), "=f"(hi) : "l"(v));
}
__device__ __forceinline__ u64 fma2(u64 a, u64 b, u64 c) {
    u64 d; asm("fma.rn.f32x2 %0, %1, %2, %3;" : "=l"(d) : "l"(a), "l"(b), "l"(c)); return d;
}
__device__ __forceinline__ u64 add2(u64 a, u64 b) {
    u64 d; asm("add.rn.f32x2 %0, %1, %2;" : "=l"(d) : "l"(a), "l"(b)); return d;
}
__device__ __forceinline__ u64 mul2(u64 a, u64 b) {
    u64 d; asm("mul.rn.f32x2 %0, %1, %2;" : "=l"(d) : "l"(a), "l"(b)); return d;
}

// ---- scratch ----
__device__ float g_h  [NMAX * DFULL];
__device__ float g_xn0[NMAX * DFULL];
__device__ float g_xn1[NMAX * DFULL];
__device__ float g_u  [NMAX * DFULL];
__device__ float g_T  [NMAX * DD];
__device__ unsigned char g_arg[NMAX * CUTN];
__device__ float g_attn_part[2560];
__device__ int   g_odd_nonzero = 0;  // monotone 0->1; set each run before consumers

// =====================================================================
// K1: h = x @ pca_w + pca_b. BM=64, BN=128, BK=16, 256 thr.
// No min-blocks clamp: regs ~80 -> 3 blocks/SM -> 313 blocks in ONE
// wave (no tail) + more latency-hiding warps.
// nb dtype detection folded into the prologue.
// =====================================================================
__global__ void __launch_bounds__(256)
k_gemm_pca(const float* __restrict__ x,
           const float* __restrict__ W,
           const float* __restrict__ bias,
           const int* __restrict__ nb32,
           int n_pairs,
           int n)
{
    __shared__ float As[2][16][72];
    __shared__ float Bs[2][16][128];

    int tid = threadIdx.x;
    int tx = tid & 15;
    int ty = tid >> 4;
    int row0 = blockIdx.x * 64;

    // folded nb dtype detection
    {
        int base = (blockIdx.x * blockDim.x + tid) * 4;
        int found = 0;
#pragma unroll
        for (int i = 0; i < 4; i++) {
            int p = base + i;
            if (p < n_pairs && nb32[2 * p + 1] != 0) found = 1;
        }
        if (found) atomicOr(&g_odd_nonzero, 1);
    }

    const int NT = (NFEAT + 15) / 16;

    float4 ra, rb[2];
    auto load_regs = [&](int kt) {
        {
            int r = tid >> 2;
            int q = (tid & 3) * 4;
            int grow = row0 + r;
            int col = kt + q;
            float4 v = make_float4(0.f, 0.f, 0.f, 0.f);
            if (grow < n && col + 3 < NFEAT)
                v = *(const float4*)(x + (size_t)grow * NFEAT + col);
            ra = v;
        }
#pragma unroll
        for (int i = 0; i < 2; i++) {
            int idx = tid * 2 + i;
            int rr = idx >> 5;
            int cq = (idx & 31) * 4;
            float4 w4 = make_float4(0.f, 0.f, 0.f, 0.f);
            if (kt + rr < NFEAT)
                w4 = *(const float4*)(W + (size_t)(kt + rr) * DFULL + cq);
            rb[i] = w4;
        }
    };
    auto store_smem = [&](int buf) {
        {
            int r = tid >> 2;
            int q = (tid & 3) * 4;
            As[buf][q + 0][r] = ra.x; As[buf][q + 1][r] = ra.y;
            As[buf][q + 2][r] = ra.z; As[buf][q + 3][r] = ra.w;
        }
#pragma unroll
        for (int i = 0; i < 2; i++) {
            int idx = tid * 2 + i;
            int rr = idx >> 5;
            int cq = (idx & 31) * 4;
            *(float4*)&Bs[buf][rr][cq] = rb[i];
        }
    };

    u64 acc2[4][4];
#pragma unroll
    for (int r = 0; r < 4; r++)
#pragma unroll
        for (int cp = 0; cp < 4; cp++) acc2[r][cp] = 0ull;

    load_regs(0);
    store_smem(0);
    __syncthreads();

    for (int t = 0; t < NT; t++) {
        int cur = t & 1;
        if (t + 1 < NT) load_regs((t + 1) * 16);

#pragma unroll
        for (int kk = 0; kk < 16; kk++) {
            float4 a4 = *(float4*)&As[cur][kk][ty * 4];
            u64 ad[4];
            ad[0] = pack2(a4.x, a4.x); ad[1] = pack2(a4.y, a4.y);
            ad[2] = pack2(a4.z, a4.z); ad[3] = pack2(a4.w, a4.w);
            ulonglong2 bp0 = *(ulonglong2*)&Bs[cur][kk][tx * 8];
            ulonglong2 bp1 = *(ulonglong2*)&Bs[cur][kk][tx * 8 + 4];
            u64 bd[4] = {bp0.x, bp0.y, bp1.x, bp1.y};
#pragma unroll
            for (int r = 0; r < 4; r++)
#pragma unroll
                for (int cp = 0; cp < 4; cp++)
                    acc2[r][cp] = fma2(ad[r], bd[cp], acc2[r][cp]);
        }

        if (t + 1 < NT) store_smem(cur ^ 1);
        __syncthreads();
    }

    float4 b0 = *(const float4*)(bias + tx * 8);
    float4 b1 = *(const float4*)(bias + tx * 8 + 4);
    u64 bb[4] = {pack2(b0.x, b0.y), pack2(b0.z, b0.w),
                 pack2(b1.x, b1.y), pack2(b1.z, b1.w)};
#pragma unroll
    for (int r = 0; r < 4; r++) {
        int grow = row0 + ty * 4 + r;
        if (grow < n) {
            ulonglong2 o0, o1;
            o0.x = add2(acc2[r][0], bb[0]); o0.y = add2(acc2[r][1], bb[1]);
            o1.x = add2(acc2[r][2], bb[2]); o1.y = add2(acc2[r][3], bb[3]);
            *(ulonglong2*)(g_h + (size_t)grow * DFULL + tx * 8)     = o0;
            *(ulonglong2*)(g_h + (size_t)grow * DFULL + tx * 8 + 4) = o1;
        }
    }
}

// =====================================================================
// K2: attention loss + xn0 = normalize(relu(h)).
// Block partial -> g_attn_part[blockIdx] (no global atomic contention).
// =====================================================================
__global__ void k_attn_xn0(const float* __restrict__ ln_g,
                           const float* __restrict__ ln_b,
                           const float* __restrict__ wqs,
                           const float* __restrict__ wks,
                           int n)
{
    __shared__ float sQ[8][128];
    __shared__ float sH[8][128];
    __shared__ float sS[8][64];
    __shared__ float s_wq[256], s_wk[256];
    __shared__ float s_g[16], s_b[16];
    __shared__ float blk_acc;

    int tid = threadIdx.x;
    { s_wq[tid] = wqs[tid]; s_wk[tid] = wks[tid]; }
    if (tid < 16)  { s_g[tid] = ln_g[tid]; s_b[tid] = ln_b[tid]; }
    if (tid == 0)  blk_acc = 0.f;
    __syncthreads();

    int wp = tid >> 5, lane = tid & 31;
    int v = blockIdx.x * 8 + wp;
    if (v < n) {
        int a  = lane >> 2;
        int c0 = (lane & 3) * 4;
        float4 h4 = *(const float4*)(g_h + (size_t)v * DFULL + lane * 4);
        float hv[4] = {h4.x, h4.y, h4.z, h4.w};

        float s1 = hv[0] + hv[1] + hv[2] + hv[3];
        float s2 = hv[0]*hv[0] + hv[1]*hv[1] + hv[2]*hv[2] + hv[3]*hv[3];
        s1 += __shfl_xor_sync(0xffffffffu, s1, 1);
        s1 += __shfl_xor_sync(0xffffffffu, s1, 2);
        s2 += __shfl_xor_sync(0xffffffffu, s2, 1);
        s2 += __shfl_xor_sync(0xffffffffu, s2, 2);
        float mu  = s1 * (1.f / 16.f);
        float var = s2 * (1.f / 16.f) - mu * mu;
        float inv = rsqrtf(var + 1e-6f);
        float qn[4];
#pragma unroll
        for (int i = 0; i < 4; i++)
            qn[i] = (hv[i] - mu) * inv * s_g[c0 + i] + s_b[c0 + i];

#pragma unroll
        for (int i = 0; i < 4; i++) {
            sQ[wp][lane * 4 + i] = qn[i];
            sH[wp][lane * 4 + i] = hv[i];
        }
        __syncwarp();

        float q4[4] = {0.f, 0.f, 0.f, 0.f};
        float k4[4] = {0.f, 0.f, 0.f, 0.f};
#pragma unroll
        for (int j = 0; j < 16; j++) {
            float qa = sQ[wp][a * 16 + j];
            float ha = sH[wp][a * 16 + j];
#pragma unroll
            for (int i = 0; i < 4; i++) {
                q4[i] = fmaf(qa, s_wq[j * 16 + c0 + i], q4[i]);
                k4[i] = fmaf(ha, s_wk[j * 16 + c0 + i], k4[i]);
            }
        }
        __syncwarp();
#pragma unroll
        for (int i = 0; i < 4; i++) {
            sQ[wp][lane * 4 + i] = q4[i];
            sH[wp][lane * 4 + i] = k4[i];
        }
        __syncwarp();

        float sc[2];
#pragma unroll
        for (int r = 0; r < 2; r++) {
            int id = lane * 2 + r;
            int aa = id >> 3, bb = id & 7;
            float s = 0.f;
#pragma unroll
            for (int c = 0; c < 16; c++)
                s = fmaf(sQ[wp][aa * 16 + c], sH[wp][bb * 16 + c], s);
            sc[r] = s * 0.25f;
        }
        sS[wp][lane * 2 + 0] = sc[0];
        sS[wp][lane * 2 + 1] = sc[1];
        __syncwarp();

        float contrib = 0.f;
        if (lane < 8) {
            float mx = -1e30f;
#pragma unroll
            for (int b = 0; b < 8; b++) mx = fmaxf(mx, sS[wp][lane * 8 + b]);
            float sum = 0.f;
#pragma unroll
            for (int b = 0; b < 8; b++) sum += expf(sS[wp][lane * 8 + b] - mx);
            float diag = expf(sS[wp][lane * 8 + lane] - mx) / sum;
            contrib = 1.f - diag;
        }
        contrib += __shfl_xor_sync(0xffffffffu, contrib, 1);
        contrib += __shfl_xor_sync(0xffffffffu, contrib, 2);
        contrib += __shfl_xor_sync(0xffffffffu, contrib, 4);
        if (lane == 0) atomicAdd(&blk_acc, contrib);

        float r4[4];
#pragma unroll
        for (int i = 0; i < 4; i++) r4[i] = fmaxf(hv[i], 0.f);
        float ss = r4[0]*r4[0] + r4[1]*r4[1] + r4[2]*r4[2] + r4[3]*r4[3];
        ss += __shfl_xor_sync(0xffffffffu, ss, 1);
        ss += __shfl_xor_sync(0xffffffffu, ss, 2);
        float scale = 1.f / fmaxf(sqrtf(ss), 1e-12f);
        float4 o = make_float4(r4[0]*scale, r4[1]*scale, r4[2]*scale, r4[3]*scale);
        *(float4*)(g_xn0 + (size_t)v * DFULL + lane * 4) = o;
    }
    __syncthreads();
    if (tid == 0) g_attn_part[blockIdx.x] = blk_acc;
}

// =====================================================================
// K3/K4: routing — EXACT R12 dataflow (known-good, ~121us/layer).
// =====================================================================
template <bool LAST>
__global__ void __launch_bounds__(128)
k_routing(const float* __restrict__ xn,
          const int* __restrict__ nb32,
          float* __restrict__ xn_out,
          int n)
{
    __shared__ float part[2][2][2][8][16];   // [buf][node][w][k][c]

    int t = threadIdx.x;
    int node = t >> 6;
    int w = (t >> 5) & 1;
    int lane = t & 31;
    int g = lane >> 3;
    int k = lane & 7;

    int v = blockIdx.x * 2 + node;
    bool valid = v < n;
    int vv = valid ? v : (n - 1);
    int st = g_odd_nonzero ? 1 : 2;

    float4 x3q4 = *(const float4*)(xn + (size_t)vv * DFULL + k * DD + g * 4);
    float x3q[4] = {x3q4.x, x3q4.y, x3q4.z, x3q4.w};

    u64 z2[4][8];
#pragma unroll
    for (int mm = 0; mm < 4; mm++) {
        int m = w * 16 + mm * 4 + g;
        int nbv = nb32[((size_t)vv * MNB + m) * (size_t)st];
        if (nbv >= 0) {
            const float* base = xn + (size_t)nbv * DFULL + k * DD;
#pragma unroll
            for (int q = 0; q < 4; q++) {
                int qg = g ^ q;
                float4 t4 = *(const float4*)(base + qg * 4);
                z2[mm][q * 2]     = pack2(t4.x, t4.y);
                z2[mm][q * 2 + 1] = pack2(t4.z, t4.w);
            }
        } else {
#pragma unroll
            for (int i = 0; i < 8; i++) z2[mm][i] = 0ull;
        }
    }

    u64 u2[8];
#pragma unroll
    for (int i = 0; i < 8; i++) u2[i] = 0ull;
    float nsq = 0.f;

    const u64 c0125 = pack2(0.125f, 0.125f);

    for (int it = 0; it < RIT; it++) {
        u64 acc2[8];
        if (it == 0) {
#pragma unroll
            for (int c = 0; c < 8; c++)
                acc2[c] = mul2(add2(add2(z2[0][c], z2[1][c]),
                                    add2(z2[2][c], z2[3][c])), c0125);
        } else {
            float invn = rsqrtf(fmaxf(nsq, 1e-24f));

            float s[4];
#pragma unroll
            for (int mm = 0; mm < 4; mm++) {
                u64 d0 = mul2(z2[mm][0], u2[0]);
                u64 d1 = mul2(z2[mm][1], u2[1]);
                d0 = fma2(z2[mm][2], u2[2], d0);
                d1 = fma2(z2[mm][3], u2[3], d1);
                d0 = fma2(z2[mm][4], u2[4], d0);
                d1 = fma2(z2[mm][5], u2[5], d1);
                d0 = fma2(z2[mm][6], u2[6], d0);
                d1 = fma2(z2[mm][7], u2[7], d1);
                d0 = add2(d0, d1);
                float lo, hi; unpack2(d0, lo, hi);
                s[mm] = (lo + hi) * invn;
            }

            if (LAST && it == RIT - 1 && w == 0) {
#pragma unroll
                for (int mm = 0; mm < 2; mm++) {
                    float bs = s[mm]; int bk = k;
#pragma unroll
                    for (int d2 = 1; d2 <= 4; d2 <<= 1) {
                        float os = __shfl_xor_sync(0xffffffffu, bs, d2);
                        int   ok = __shfl_xor_sync(0xffffffffu, bk, d2);
                        if (os > bs || (os == bs && ok < bk)) { bs = os; bk = ok; }
                    }
                    int m = mm * 4 + g;
                    if (k == 0 && m < CUTN && valid)
                        g_arg[(size_t)v * CUTN + m] = (unsigned char)bk;
                }
            }

            float p[4];
#pragma unroll
            for (int mm = 0; mm < 4; mm++) {
                float e = __expf(s[mm]);
                float sum = e;
                sum += __shfl_xor_sync(0xffffffffu, sum, 1);
                sum += __shfl_xor_sync(0xffffffffu, sum, 2);
                sum += __shfl_xor_sync(0xffffffffu, sum, 4);
                p[mm] = __fdividef(e, sum);
            }
            u64 p2[4];
#pragma unroll
            for (int mm = 0; mm < 4; mm++) p2[mm] = pack2(p[mm], p[mm]);
#pragma unroll
            for (int c = 0; c < 8; c++)
                acc2[c] = fma2(p2[0], z2[0][c],
                          fma2(p2[1], z2[1][c],
                          fma2(p2[2], z2[2][c], mul2(p2[3], z2[3][c]))));
        }

        float acc[16];
#pragma unroll
        for (int c = 0; c < 8; c++) unpack2(acc2[c], acc[2*c], acc[2*c+1]);

        float red[8];
#pragma unroll
        for (int j = 0; j < 8; j++)
            red[j] = acc[j] + __shfl_xor_sync(0xffffffffu, acc[8 + j], 16);
        float quad[4];
#pragma unroll
        for (int j = 0; j < 4; j++)
            quad[j] = red[j] + __shfl_xor_sync(0xffffffffu, red[4 + j], 8);

        int buf = it & 1;
        *(float4*)&part[buf][node][w][k][g * 4] =
            make_float4(quad[0], quad[1], quad[2], quad[3]);
        __syncthreads();

        float4 o4 = *(float4*)&part[buf][node][1 - w][k][g * 4];
        float oq[4] = {quad[0] + o4.x + x3q[0], quad[1] + o4.y + x3q[1],
                       quad[2] + o4.z + x3q[2], quad[3] + o4.w + x3q[3]};

        if (it == RIT - 1) {
            if (valid && w == 0) {
                if (LAST) {
                    *(float4*)(g_u + (size_t)v * DFULL + k * DD + g * 4) =
                        make_float4(oq[0], oq[1], oq[2], oq[3]);
                } else {
                    float r0 = fmaxf(oq[0], 0.f), r1 = fmaxf(oq[1], 0.f);
                    float r2 = fmaxf(oq[2], 0.f), r3 = fmaxf(oq[3], 0.f);
                    float ssr = r0*r0 + r1*r1 + r2*r2 + r3*r3;
                    ssr += __shfl_xor_sync(0xffffffffu, ssr, 8);
                    ssr += __shfl_xor_sync(0xffffffffu, ssr, 16);
                    float sc = rsqrtf(fmaxf(ssr, 1e-24f));
                    *(float4*)(xn_out + (size_t)v * DFULL + k * DD + g * 4) =
                        make_float4(r0*sc, r1*sc, r2*sc, r3*sc);
                }
            }
        } else {
            float np = oq[0]*oq[0] + oq[1]*oq[1] + oq[2]*oq[2] + oq[3]*oq[3];
            np += __shfl_xor_sync(0xffffffffu, np, 8);
            np += __shfl_xor_sync(0xffffffffu, np, 16);
            nsq = np;

            float h8[8], f16[16];
#pragma unroll
            for (int j = 0; j < 4; j++) {
                h8[j] = oq[j];
                h8[4 + j] = __shfl_xor_sync(0xffffffffu, oq[j], 8);
            }
#pragma unroll
            for (int j = 0; j < 8; j++) {
                f16[j] = h8[j];
                f16[8 + j] = __shfl_xor_sync(0xffffffffu, h8[j], 16);
            }
#pragma unroll
            for (int i = 0; i < 8; i++)
                u2[i] = pack2(f16[2*i], f16[2*i + 1]);
        }
    }
}

// =====================================================================
// K5: T[w,:] = sum_{j<5} xn1[nb[w,j], arg[w,j], :]
// =====================================================================
__global__ void k_compute_T(const int* __restrict__ nb32, int n)
{
    int tid = blockIdx.x * blockDim.x + threadIdx.x;
    if (tid >= n * DD) return;
    int w = tid >> 4, c = tid & 15;
    int st = g_odd_nonzero ? 1 : 2;
    float s = 0.f;
#pragma unroll
    for (int j = 0; j < CUTN; j++) {
        int nv = nb32[((size_t)w * MNB + j) * (size_t)st];
        if (nv >= 0) {
            int a = g_arg[(size_t)w * CUTN + j];
            s += g_xn1[(size_t)nv * DFULL + a * DD + c];
        }
    }
    g_T[tid] = s;
}

// =====================================================================
// K6: meta + logits + log_softmax + attn scalar (reduces g_attn_part).
// Logit dot split across all 32 lanes (R16, validated).
// =====================================================================
__global__ void k_meta_out(const int* __restrict__ nb32,
                           const float* __restrict__ mlp_w,
                           const float* __restrict__ mlp_b,
                           float* __restrict__ out,
                           int n, int nblk)
{
    __shared__ float s_w[128 * 16];
    __shared__ float s_b[16];
    __shared__ float sM[8][128];

    int tid = threadIdx.x;
    for (int i = tid; i < 2048; i += 256) s_w[i] = mlp_w[i];
    if (tid < 16) s_b[tid] = mlp_b[tid];
    __syncthreads();

    if (blockIdx.x == 0 && tid < 32) {
        float s = 0.f;
        for (int i = tid; i < nblk; i += 32) s += g_attn_part[i];
        s += __shfl_xor_sync(0xffffffffu, s, 16);
        s += __shfl_xor_sync(0xffffffffu, s, 8);
        s += __shfl_xor_sync(0xffffffffu, s, 4);
        s += __shfl_xor_sync(0xffffffffu, s, 2);
        s += __shfl_xor_sync(0xffffffffu, s, 1);
        if (tid == 0) out[(size_t)n * 16] = s / (56.f * (float)n);
    }

    int st = g_odd_nonzero ? 1 : 2;
    int wp = tid >> 5, lane = tid & 31;
    int v = blockIdx.x * 8 + wp;
    if (v < n) {
        int a = lane >> 2;
        float4 acc = *(const float4*)(g_u + (size_t)v * DFULL + lane * 4);
        const float inv25 = 1.f / 25.f;
#pragma unroll
        for (int j = 0; j < CUTN; j++) {
            int nv = nb32[((size_t)v * MNB + j) * (size_t)st];
            if (nv >= 0) {
                int aj = g_arg[(size_t)v * CUTN + j];
                if (aj == a) {
                    float4 t4 = *(const float4*)(g_T + (size_t)nv * DD + (lane & 3) * 4);
                    acc.x = fmaf(inv25, t4.x, acc.x);
                    acc.y = fmaf(inv25, t4.y, acc.y);
                    acc.z = fmaf(inv25, t4.z, acc.z);
                    acc.w = fmaf(inv25, t4.w, acc.w);
                }
            }
        }
        acc.x = fmaxf(acc.x, 0.f); acc.y = fmaxf(acc.y, 0.f);
        acc.z = fmaxf(acc.z, 0.f); acc.w = fmaxf(acc.w, 0.f);
        *(float4*)&sM[wp][lane * 4] = acc;
        __syncwarp();

        int hh = lane >> 4;
        int cc = lane & 15;
        float part = 0.f;
        int f0 = hh * 64;
#pragma unroll 16
        for (int f = 0; f < 64; f++)
            part = fmaf(sM[wp][f0 + f], s_w[(f0 + f) * 16 + cc], part);
        float logit = part + __shfl_xor_sync(0xffffffffu, part, 16) + s_b[cc];

        if (lane < 16)
            out[(size_t)n * 16 + 1 + (size_t)v * 16 + lane] = logit;

        float mx = (lane < 16) ? logit : -1e30f;
        mx = fmaxf(mx, __shfl_xor_sync(0xffffffffu, mx, 1));
        mx = fmaxf(mx, __shfl_xor_sync(0xffffffffu, mx, 2));
        mx = fmaxf(mx, __shfl_xor_sync(0xffffffffu, mx, 4));
        mx = fmaxf(mx, __shfl_xor_sync(0xffffffffu, mx, 8));
        float e = (lane < 16) ? expf(logit - mx) : 0.f;
        float sum = e;
        sum += __shfl_xor_sync(0xffffffffu, sum, 1);
        sum += __shfl_xor_sync(0xffffffffu, sum, 2);
        sum += __shfl_xor_sync(0xffffffffu, sum, 4);
        sum += __shfl_xor_sync(0xffffffffu, sum, 8);
        if (lane < 16)
            out[(size_t)v * 16 + lane] = (logit - mx) - logf(sum);
    }
}

// =====================================================================
extern "C" void kernel_launch(void* const* d_in, const int* in_sizes, int n_in,
                              void* d_out, int out_size)
{
    const float* x     = (const float*)d_in[0];
    const int*   nb32  = (const int*)d_in[1];
    const float* pca_w = (const float*)d_in[2];
    const float* pca_b = (const float*)d_in[3];
    const float* ln_g  = (const float*)d_in[4];
    const float* ln_b  = (const float*)d_in[5];
    const float* w_qs  = (const float*)d_in[6];
    const float* w_ks  = (const float*)d_in[7];
    const float* mlp_w = (const float*)d_in[8];
    const float* mlp_b = (const float*)d_in[9];
    float* out = (float*)d_out;

    int n = in_sizes[0] / NFEAT;   // 20000
    int n_nb = in_sizes[1];
    int nblk_attn = (n + 7) / 8;   // 2500

    float* p_xn0; cudaGetSymbolAddress((void**)&p_xn0, g_xn0);
    float* p_xn1; cudaGetSymbolAddress((void**)&p_xn1, g_xn1);

    k_gemm_pca<<<(n + 63) / 64, 256>>>(x, pca_w, pca_b, nb32, n_nb / 2, n);
    k_attn_xn0<<<nblk_attn, 256>>>(ln_g, ln_b, w_qs, w_ks, n);
    k_routing<false><<<(n + 1) / 2, 128>>>(p_xn0, nb32, p_xn1, n);
    k_routing<true ><<<(n + 1) / 2, 128>>>(p_xn1, nb32, nullptr, n);
    k_compute_T<<<(n * DD + 255) / 256, 256>>>(nb32, n);
    k_meta_out<<<(n + 7) / 8, 256>>>(nb32, mlp_w, mlp_b, out, n, nblk_attn);
}